// round 14
// baseline (speedup 1.0000x reference)
#include <cuda_runtime.h>
#include <math.h>

#define HW 4096
#define BATCH 2

typedef unsigned long long ull;

// Scratch (device globals — no allocation allowed)
__device__ float g_qkv[BATCH * 288 * HW];  // rows: 0-95 Q, 96-191 K, 192-287 V
__device__ float g_att[BATCH * 288 * HW];  // channel = head*72 + range*24 + d
__device__ float g_lex[BATCH * 4 * HW];    // per-(b,head,px) boundary l exchange

// ---------------------------------------------------------------------------
// f32x2 helpers
// ---------------------------------------------------------------------------
__device__ __forceinline__ ull pk2(float a) {
    ull r; asm("mov.b64 %0, {%1,%1};" : "=l"(r) : "f"(a)); return r;
}
__device__ __forceinline__ ull pkpair(float lo, float hi) {
    ull r; asm("mov.b64 %0, {%1,%2};" : "=l"(r) : "f"(lo), "f"(hi)); return r;
}
__device__ __forceinline__ ull ffma2(ull a, ull b, ull c) {
    ull d; asm("fma.rn.f32x2 %0, %1, %2, %3;" : "=l"(d) : "l"(a), "l"(b), "l"(c)); return d;
}
__device__ __forceinline__ ull add2(ull a, ull b) {
    ull d; asm("add.rn.f32x2 %0, %1, %2;" : "=l"(d) : "l"(a), "l"(b)); return d;
}
__device__ __forceinline__ void upk(ull v, float& lo, float& hi) {
    asm("mov.b64 {%0,%1}, %2;" : "=f"(lo), "=f"(hi) : "l"(v));
}

// ---------------------------------------------------------------------------
// GEMM (f32x2), DOUBLE-BUFFERED, BK=16 (R10 proven skeleton):
// C[m][pix] = f( sum_{k in [kbeg, kbeg+KCHUNK)} W[m][k] * X[k][pix] )
// MODE 0: fused QKV (z selects W/bias/C), bias added, kbeg=0.
// MODE 1: chunk write: C = bias + partial.
// MODE 2: chunk accumulate: C += partial (reads existing C).
// BM=96, BN=64, 128 threads, TM=6, TN=8.
// ---------------------------------------------------------------------------
#define WSTR 102

template <int KTOT, int KCHUNK, int MODE>
__global__ __launch_bounds__(128) void gemm_k(
    const float* __restrict__ X, long xstride, long cstride,
    const float* w0, const float* w1, const float* w2,
    const float* b0, const float* b1, const float* b2,
    float* c0, float* c1, float* c2, int kbeg)
{
    const int z = blockIdx.z;
    const float* __restrict__ W;
    const float* __restrict__ bias;
    float* __restrict__ C;
    if (MODE == 0) {
        W    = (z == 0) ? w0 : ((z == 1) ? w1 : w2);
        bias = (z == 0) ? b0 : ((z == 1) ? b1 : b2);
        C    = (z == 0) ? c0 : ((z == 1) ? c1 : c2);
    } else {
        W = w0; bias = b0; C = c0;
    }
    C += (long)blockIdx.y * cstride;
    const float* __restrict__ Xb = X + (long)blockIdx.y * xstride;

    __shared__ float Ws[2][16][WSTR];
    __shared__ float Xs[2][16][64];

    const int tid = threadIdx.x;
    const int tx = tid & 7;
    const int ty = tid >> 3;
    const int n0 = blockIdx.x * 64;

    int wm[3], wk[3], xr[2], xc[2];
    #pragma unroll
    for (int i = 0; i < 3; i++) {
        int idx = tid + i * 128;
        wm[i] = idx >> 2;
        wk[i] = (idx & 3) * 4;
    }
    #pragma unroll
    for (int i = 0; i < 2; i++) {
        int idx = tid + i * 128;
        xr[i] = idx >> 4;
        xc[i] = (idx & 15) * 4;
    }

    ull acc[6][4] = {};

    #pragma unroll
    for (int i = 0; i < 3; i++) {
        float4 w = *(const float4*)&W[(long)wm[i] * KTOT + kbeg + wk[i]];
        Ws[0][wk[i] + 0][wm[i]] = w.x;
        Ws[0][wk[i] + 1][wm[i]] = w.y;
        Ws[0][wk[i] + 2][wm[i]] = w.z;
        Ws[0][wk[i] + 3][wm[i]] = w.w;
    }
    #pragma unroll
    for (int i = 0; i < 2; i++)
        *(float4*)&Xs[0][xr[i]][xc[i]] =
            *(const float4*)&Xb[(long)(kbeg + xr[i]) * HW + n0 + xc[i]];
    __syncthreads();

    const int NT = KCHUNK / 16;
    #pragma unroll 1
    for (int t = 0; t < NT; t++) {
        const int cur = t & 1;
        const bool more = (t + 1 < NT);
        const int k1 = kbeg + (t + 1) * 16;

        float4 wpre[3], xpre[2];
        if (more) {
            #pragma unroll
            for (int i = 0; i < 3; i++)
                wpre[i] = *(const float4*)&W[(long)wm[i] * KTOT + k1 + wk[i]];
            #pragma unroll
            for (int i = 0; i < 2; i++)
                xpre[i] = *(const float4*)&Xb[(long)(k1 + xr[i]) * HW + n0 + xc[i]];
        }

        #pragma unroll
        for (int kk = 0; kk < 16; kk++) {
            float2 a01 = *(float2*)&Ws[cur][kk][ty * 6];
            float2 a23 = *(float2*)&Ws[cur][kk][ty * 6 + 2];
            float2 a45 = *(float2*)&Ws[cur][kk][ty * 6 + 4];
            ull ad[6] = {pk2(a01.x), pk2(a01.y), pk2(a23.x),
                         pk2(a23.y), pk2(a45.x), pk2(a45.y)};
            ulonglong2 x0 = *(ulonglong2*)&Xs[cur][kk][tx * 8];
            ulonglong2 x1 = *(ulonglong2*)&Xs[cur][kk][tx * 8 + 4];
            ull bq[4] = {x0.x, x0.y, x1.x, x1.y};
            #pragma unroll
            for (int i = 0; i < 6; i++)
                #pragma unroll
                for (int j = 0; j < 4; j++)
                    acc[i][j] = ffma2(ad[i], bq[j], acc[i][j]);
        }

        if (more) {
            #pragma unroll
            for (int i = 0; i < 3; i++) {
                Ws[1 - cur][wk[i] + 0][wm[i]] = wpre[i].x;
                Ws[1 - cur][wk[i] + 1][wm[i]] = wpre[i].y;
                Ws[1 - cur][wk[i] + 2][wm[i]] = wpre[i].z;
                Ws[1 - cur][wk[i] + 3][wm[i]] = wpre[i].w;
            }
            #pragma unroll
            for (int i = 0; i < 2; i++)
                *(float4*)&Xs[1 - cur][xr[i]][xc[i]] = xpre[i];
        }
        __syncthreads();
    }

    #pragma unroll
    for (int i = 0; i < 6; i++) {
        int m = ty * 6 + i;
        float* cp = &C[(long)m * HW + n0 + tx * 8];
        float4 o0, o1;
        upk(acc[i][0], o0.x, o0.y);
        upk(acc[i][1], o0.z, o0.w);
        upk(acc[i][2], o1.x, o1.y);
        upk(acc[i][3], o1.z, o1.w);
        if (MODE == 2) {
            float4 e0 = *(float4*)cp;
            float4 e1 = *(float4*)(cp + 4);
            o0.x += e0.x; o0.y += e0.y; o0.z += e0.z; o0.w += e0.w;
            o1.x += e1.x; o1.y += e1.y; o1.z += e1.z; o1.w += e1.w;
        } else {
            float bv = bias[m];
            o0.x += bv; o0.y += bv; o0.z += bv; o0.w += bv;
            o1.x += bv; o1.y += bv; o1.z += bv; o1.w += bv;
        }
        *(float4*)cp = o0;
        *(float4*)(cp + 4) = o1;
    }
}

// ---------------------------------------------------------------------------
// Attention v8 (R13 proven, byte-identical): VERTICAL pixel pairs + ROLLING
// accumulator. 8x16 tile; 128 threads = 64 pairs x 2 roles.
// ---------------------------------------------------------------------------
#define PSTR 28
#define HROWS 18
#define HCOLS 26
#define HPX (HROWS * HCOLS)              // 468
#define ATTN_SMEM (2 * HPX * PSTR * 4)   // 104832 B

__global__ __launch_bounds__(128, 2) void attn_kernel()
{
    extern __shared__ float sh[];
    float* Ksh = sh;
    float* Vsh = sh + HPX * PSTR;

    const int head = blockIdx.y;
    const int b = blockIdx.z;
    const int th = (blockIdx.x >> 2) * 8;
    const int tw = (blockIdx.x & 3) * 16;
    const int h0 = th - 5, w0 = tw - 5;

    const float* base = g_qkv + (long)b * 288 * HW;
    const float* Kg = base + (96 + head * 24) * HW;
    const float* Vg = base + (192 + head * 24) * HW;

    const int tid = threadIdx.x;

    {
        int po[4]; int gi[4]; bool ok[4]; int cnt = 0;
        for (int p = tid; p < HPX; p += 128) {
            int py = p / HCOLS, px = p - py * HCOLS;
            int gy = h0 + py, gx = w0 + px;
            po[cnt] = p * PSTR;
            ok[cnt] = ((unsigned)gy < 64u) && ((unsigned)gx < 64u);
            gi[cnt] = ok[cnt] ? (gy * 64 + gx) : 0;
            cnt++;
        }
        #pragma unroll 4
        for (int d = 0; d < 24; d++) {
            long doff = (long)d * HW;
            #pragma unroll
            for (int n = 0; n < 4; n++) {
                if (n < cnt) {
                    float kv = ok[n] ? Kg[doff + gi[n]] : 0.f;
                    float vv = ok[n] ? Vg[doff + gi[n]] : 0.f;
                    Ksh[po[n] + d] = kv;
                    Vsh[po[n] + d] = vv;
                }
            }
        }
    }
    __syncthreads();

    const int role = tid >> 6;            // 0: dy<=0, 1: dy>=1
    const int pid = tid & 63;             // pair id
    const int pr = pid >> 4;              // 0..3 (A row = 2*pr)
    const int px = pid & 15;
    const int rowA = 2 * pr;

    const float* QgA = g_qkv + ((long)b * 288 + head * 24) * HW + (th + rowA) * 64 + (tw + px);
    ull q2A[12], q2B[12];
    #pragma unroll
    for (int j = 0; j < 12; j++) {
        const float sc = 0.2041241452319315f;
        q2A[j] = pkpair(QgA[(long)(2 * j) * HW] * sc,      QgA[(long)(2 * j + 1) * HW] * sc);
        q2B[j] = pkpair(QgA[(long)(2 * j) * HW + 64] * sc, QgA[(long)(2 * j + 1) * HW + 64] * sc);
    }

    ull accA[12] = {}, accB[12] = {}, nxt[12] = {};
    float lA = 0.f, lB = 0.f, lnx = 0.f;
    const int cbase = (rowA + 5) * HCOLS + (px + 5);

    float* A = g_att + ((long)b * 288 + head * 72) * HW + (th + rowA) * 64 + (tw + px);
    const int lidxA = ((b * 4 + head) * HW) + (th + rowA) * 64 + (tw + px);

#define SITE2(POFF, ACA, LA_, ACB, LB_) { \
    const ulonglong2* kp = (const ulonglong2*)(Ksh + (cbase + (POFF)) * PSTR); \
    const ulonglong2* vp = (const ulonglong2*)(Vsh + (cbase + (POFF)) * PSTR); \
    ulonglong2 k0 = kp[0], k1 = kp[1], k2 = kp[2]; \
    ulonglong2 k3 = kp[3], k4 = kp[4], k5 = kp[5]; \
    ull sa = 0ULL, sb = 0ULL, ta = 0ULL, tb = 0ULL; \
    sa = ffma2(q2A[0], k0.x, sa);   sb = ffma2(q2A[1], k0.y, sb); \
    ta = ffma2(q2B[0], k0.x, ta);   tb = ffma2(q2B[1], k0.y, tb); \
    sa = ffma2(q2A[2], k1.x, sa);   sb = ffma2(q2A[3], k1.y, sb); \
    ta = ffma2(q2B[2], k1.x, ta);   tb = ffma2(q2B[3], k1.y, tb); \
    sa = ffma2(q2A[4], k2.x, sa);   sb = ffma2(q2A[5], k2.y, sb); \
    ta = ffma2(q2B[4], k2.x, ta);   tb = ffma2(q2B[5], k2.y, tb); \
    sa = ffma2(q2A[6], k3.x, sa);   sb = ffma2(q2A[7], k3.y, sb); \
    ta = ffma2(q2B[6], k3.x, ta);   tb = ffma2(q2B[7], k3.y, tb); \
    sa = ffma2(q2A[8], k4.x, sa);   sb = ffma2(q2A[9], k4.y, sb); \
    ta = ffma2(q2B[8], k4.x, ta);   tb = ffma2(q2B[9], k4.y, tb); \
    sa = ffma2(q2A[10], k5.x, sa);  sb = ffma2(q2A[11], k5.y, sb); \
    ta = ffma2(q2B[10], k5.x, ta);  tb = ffma2(q2B[11], k5.y, tb); \
    float x0, x1, y0, y1; \
    upk(add2(sa, sb), x0, x1); upk(add2(ta, tb), y0, y1); \
    float eA = __expf(x0 + x1), eB = __expf(y0 + y1); \
    LA_ += eA; LB_ += eB; \
    ull pA = pk2(eA), pB = pk2(eB); \
    ulonglong2 v0 = vp[0], v1 = vp[1], v2 = vp[2]; \
    ulonglong2 v3 = vp[3], v4 = vp[4], v5 = vp[5]; \
    ACA[0] = ffma2(pA, v0.x, ACA[0]);   ACB[0] = ffma2(pB, v0.x, ACB[0]); \
    ACA[1] = ffma2(pA, v0.y, ACA[1]);   ACB[1] = ffma2(pB, v0.y, ACB[1]); \
    ACA[2] = ffma2(pA, v1.x, ACA[2]);   ACB[2] = ffma2(pB, v1.x, ACB[2]); \
    ACA[3] = ffma2(pA, v1.y, ACA[3]);   ACB[3] = ffma2(pB, v1.y, ACB[3]); \
    ACA[4] = ffma2(pA, v2.x, ACA[4]);   ACB[4] = ffma2(pB, v2.x, ACB[4]); \
    ACA[5] = ffma2(pA, v2.y, ACA[5]);   ACB[5] = ffma2(pB, v2.y, ACB[5]); \
    ACA[6] = ffma2(pA, v3.x, ACA[6]);   ACB[6] = ffma2(pB, v3.x, ACB[6]); \
    ACA[7] = ffma2(pA, v3.y, ACA[7]);   ACB[7] = ffma2(pB, v3.y, ACB[7]); \
    ACA[8] = ffma2(pA, v4.x, ACA[8]);   ACB[8] = ffma2(pB, v4.x, ACB[8]); \
    ACA[9] = ffma2(pA, v4.y, ACA[9]);   ACB[9] = ffma2(pB, v4.y, ACB[9]); \
    ACA[10] = ffma2(pA, v5.x, ACA[10]); ACB[10] = ffma2(pB, v5.x, ACB[10]); \
    ACA[11] = ffma2(pA, v5.y, ACA[11]); ACB[11] = ffma2(pB, v5.y, ACB[11]); \
}

#define SITE1(POFF, Q2, AC, L_) { \
    const ulonglong2* kp = (const ulonglong2*)(Ksh + (cbase + (POFF)) * PSTR); \
    const ulonglong2* vp = (const ulonglong2*)(Vsh + (cbase + (POFF)) * PSTR); \
    ulonglong2 k0 = kp[0], k1 = kp[1], k2 = kp[2]; \
    ulonglong2 k3 = kp[3], k4 = kp[4], k5 = kp[5]; \
    ull sa = 0ULL, sb = 0ULL; \
    sa = ffma2(Q2[0], k0.x, sa);  sb = ffma2(Q2[1], k0.y, sb); \
    sa = ffma2(Q2[2], k1.x, sa);  sb = ffma2(Q2[3], k1.y, sb); \
    sa = ffma2(Q2[4], k2.x, sa);  sb = ffma2(Q2[5], k2.y, sb); \
    sa = ffma2(Q2[6], k3.x, sa);  sb = ffma2(Q2[7], k3.y, sb); \
    sa = ffma2(Q2[8], k4.x, sa);  sb = ffma2(Q2[9], k4.y, sb); \
    sa = ffma2(Q2[10], k5.x, sa); sb = ffma2(Q2[11], k5.y, sb); \
    float x0, x1; upk(add2(sa, sb), x0, x1); \
    float e = __expf(x0 + x1); \
    L_ += e; ull pe = pk2(e); \
    ulonglong2 v0 = vp[0], v1 = vp[1], v2 = vp[2]; \
    ulonglong2 v3 = vp[3], v4 = vp[4], v5 = vp[5]; \
    AC[0] = ffma2(pe, v0.x, AC[0]);   AC[1]  = ffma2(pe, v0.y, AC[1]); \
    AC[2] = ffma2(pe, v1.x, AC[2]);   AC[3]  = ffma2(pe, v1.y, AC[3]); \
    AC[4] = ffma2(pe, v2.x, AC[4]);   AC[5]  = ffma2(pe, v2.y, AC[5]); \
    AC[6] = ffma2(pe, v3.x, AC[6]);   AC[7]  = ffma2(pe, v3.y, AC[7]); \
    AC[8] = ffma2(pe, v4.x, AC[8]);   AC[9]  = ffma2(pe, v4.y, AC[9]); \
    AC[10] = ffma2(pe, v5.x, AC[10]); AC[11] = ffma2(pe, v5.y, AC[11]); \
}

#define BOUNDARY(RB) { \
    __syncthreads(); \
    if (role == 1) { \
        _Pragma("unroll") \
        for (int j = 0; j < 12; j++) { \
            float lo, hi; \
            upk(accA[j], lo, hi); \
            A[(long)((RB) + 2 * j) * HW]          = lo; \
            A[(long)((RB) + 2 * j + 1) * HW]      = hi; \
            upk(accB[j], lo, hi); \
            A[(long)((RB) + 2 * j) * HW + 64]     = lo; \
            A[(long)((RB) + 2 * j + 1) * HW + 64] = hi; \
        } \
        g_lex[lidxA]      = lA; \
        g_lex[lidxA + 64] = lB; \
        _Pragma("unroll") \
        for (int j = 0; j < 12; j++) { \
            accA[j] = nxt[j]; nxt[j] = 0ULL; accB[j] = 0ULL; \
        } \
        lA = lnx; lnx = 0.f; lB = 0.f; \
    } \
    __syncthreads(); \
    if (role == 0) { \
        lA += g_lex[lidxA]; \
        lB += g_lex[lidxA + 64]; \
        float rA = __fdividef(1.f, lA); \
        float rB = __fdividef(1.f, lB); \
        _Pragma("unroll") \
        for (int j = 0; j < 12; j++) { \
            float lo, hi; \
            upk(accA[j], lo, hi); \
            lo += A[(long)((RB) + 2 * j) * HW]; \
            hi += A[(long)((RB) + 2 * j + 1) * HW]; \
            accA[j] = pkpair(lo, hi); \
            A[(long)((RB) + 2 * j) * HW]     = lo * rA; \
            A[(long)((RB) + 2 * j + 1) * HW] = hi * rA; \
            upk(accB[j], lo, hi); \
            lo += A[(long)((RB) + 2 * j) * HW + 64]; \
            hi += A[(long)((RB) + 2 * j + 1) * HW + 64]; \
            accB[j] = pkpair(lo, hi); \
            A[(long)((RB) + 2 * j) * HW + 64]     = lo * rB; \
            A[(long)((RB) + 2 * j + 1) * HW + 64] = hi * rB; \
        } \
        _Pragma("unroll") \
        for (int j = 0; j < 12; j++) { \
            accB[j] = add2(accB[j], nxt[j]); nxt[j] = 0ULL; \
        } \
        lB += lnx; lnx = 0.f; \
    } \
}

    // ===== Phase 1 (leading pixel's 7x7 core) =====
    if (role == 0) {
        #pragma unroll 2
        for (int dx = -3; dx <= 3; dx++) { SITE2(-3 * HCOLS + dx, accA, lA, nxt, lnx) }
        #pragma unroll 1
        for (int dy = -2; dy <= 0; dy++) {
            #pragma unroll 2
            for (int dx = -3; dx <= 3; dx++) { SITE2(dy * HCOLS + dx, accA, lA, accB, lB) }
        }
    } else {
        #pragma unroll 1
        for (int dy = 1; dy <= 3; dy++) {
            #pragma unroll 2
            for (int dx = -3; dx <= 3; dx++) { SITE2(dy * HCOLS + dx, accA, lA, accB, lB) }
        }
        #pragma unroll 2
        for (int dx = -3; dx <= 3; dx++) { SITE2(4 * HCOLS + dx, nxt, lnx, accB, lB) }
    }
    BOUNDARY(0)

    // ===== Phase 2 (leading pixel's 9-ring) =====
    if (role == 0) {
        #pragma unroll 2
        for (int dx = -4; dx <= 4; dx++) { SITE2(-4 * HCOLS + dx, accA, lA, nxt, lnx) }
        #pragma unroll 1
        for (int dy = -3; dy <= 0; dy++) {
            SITE2(dy * HCOLS - 4, accA, lA, accB, lB)
            SITE2(dy * HCOLS + 4, accA, lA, accB, lB)
        }
    } else {
        #pragma unroll 2
        for (int dx = -4; dx <= 4; dx++) { SITE2(5 * HCOLS + dx, nxt, lnx, accB, lB) }
        #pragma unroll 1
        for (int dy = 1; dy <= 4; dy++) {
            SITE2(dy * HCOLS - 4, accA, lA, accB, lB)
            SITE2(dy * HCOLS + 4, accA, lA, accB, lB)
        }
    }
    BOUNDARY(24)

    // ===== Phase 3 (leading pixel's 11-ring) =====
    if (role == 0) {
        #pragma unroll 2
        for (int dx = -5; dx <= 5; dx++) { SITE1(-5 * HCOLS + dx, q2A, accA, lA) }
        #pragma unroll 1
        for (int dy = -4; dy <= 0; dy++) {
            SITE2(dy * HCOLS - 5, accA, lA, accB, lB)
            SITE2(dy * HCOLS + 5, accA, lA, accB, lB)
        }
    } else {
        #pragma unroll 2
        for (int dx = -5; dx <= 5; dx++) { SITE1(6 * HCOLS + dx, q2B, accB, lB) }
        #pragma unroll 1
        for (int dy = 1; dy <= 5; dy++) {
            SITE2(dy * HCOLS - 5, accA, lA, accB, lB)
            SITE2(dy * HCOLS + 5, accA, lA, accB, lB)
        }
    }
    BOUNDARY(48)

#undef SITE2
#undef SITE1
#undef BOUNDARY
}

// ---------------------------------------------------------------------------
extern "C" void kernel_launch(void* const* d_in, const int* in_sizes, int n_in,
                              void* d_out, int out_size)
{
    const float* x  = (const float*)d_in[0];
    const float* wq = (const float*)d_in[1];
    const float* bq = (const float*)d_in[2];
    const float* wk = (const float*)d_in[3];
    const float* bk = (const float*)d_in[4];
    const float* wv = (const float*)d_in[5];
    const float* bv = (const float*)d_in[6];
    const float* wo = (const float*)d_in[7];
    const float* bo = (const float*)d_in[8];
    float* out = (float*)d_out;

    float* qkv = nullptr;
    float* att = nullptr;
    cudaGetSymbolAddress((void**)&qkv, g_qkv);
    cudaGetSymbolAddress((void**)&att, g_att);

    cudaFuncSetAttribute(attn_kernel, cudaFuncAttributeMaxDynamicSharedMemorySize, ATTN_SMEM);

    // Fused QKV: 384 CTAs, double-buffered, BK=16 (R10 proven)
    gemm_k<96, 96, 0><<<dim3(64, BATCH, 3), 128>>>(
        x, 96L * HW, 288L * HW,
        wq, wk, wv, bq, bk, bv,
        qkv, qkv + 96L * HW, qkv + 192L * HW, 0);

    // Multi-range local attention v8 (R13 proven)
    attn_kernel<<<dim3(32, 4, BATCH), 128, ATTN_SMEM>>>();

    // Output projection: sequential K-chunks, no partial slabs, no finish.
    // chunk0: out = bias + sum_{k<144}; chunk1: out += sum_{k>=144}
    gemm_k<288, 144, 1><<<dim3(64, BATCH, 1), 128>>>(
        att, 288L * HW, 96L * HW,
        wo, wo, wo, bo, bo, bo,
        out, out, out, 0);
    gemm_k<288, 144, 2><<<dim3(64, BATCH, 1), 128>>>(
        att, 288L * HW, 96L * HW,
        wo, wo, wo, bo, bo, bo,
        out, out, out, 144);
}